// round 1
// baseline (speedup 1.0000x reference)
#include <cuda_runtime.h>
#include <cuda_bf16.h>

#define N_NODES 50000
#define N_EDGES 800000
#define DIM 128
#define NEG_SLOPE 0.01f

// ---------------- scratch (device globals; no allocation allowed) ----------
__device__ float g_deg[N_NODES];
__device__ float g_rinv[N_NODES];
__device__ float g_hsum[N_NODES * DIM];
__device__ float g_ha_src[N_NODES * DIM];
__device__ float g_ha_dst[N_NODES * DIM];
__device__ float g_s[N_EDGES];
__device__ float g_denom[N_NODES];

// ---------------- init: zero everything that is accumulated ----------------
__global__ void zero_kernel(float* __restrict__ out) {
    long long stride = (long long)gridDim.x * blockDim.x;
    long long tid = (long long)blockIdx.x * blockDim.x + threadIdx.x;
    for (long long i = tid; i < (long long)N_NODES * DIM; i += stride) {
        g_hsum[i] = 0.0f;
        out[i] = 0.0f;
    }
    for (long long i = tid; i < N_NODES; i += stride) {
        g_deg[i] = 0.0f;
        g_denom[i] = 0.0f;
    }
}

// ------------- pass 1: h_sum[dst] += x[src], deg[dst] += 1 (warp/edge) -----
__global__ void edge_agg_kernel(const float* __restrict__ x,
                                const int* __restrict__ src,
                                const int* __restrict__ dst) {
    int gtid = blockIdx.x * blockDim.x + threadIdx.x;
    int e = gtid >> 5;
    int lane = threadIdx.x & 31;
    if (e >= N_EDGES) return;
    int s = src[e];
    int d = dst[e];
    float4 v = *(const float4*)&x[(long long)s * DIM + lane * 4];
    float* hp = &g_hsum[(long long)d * DIM + lane * 4];
    atomicAdd(hp + 0, v.x);
    atomicAdd(hp + 1, v.y);
    atomicAdd(hp + 2, v.z);
    atomicAdd(hp + 3, v.w);
    if (lane == 0) atomicAdd(&g_deg[d], 1.0f);
}

// ------------- compute reciprocal of clamped degree -----------------------
__global__ void rinv_kernel() {
    int i = blockIdx.x * blockDim.x + threadIdx.x;
    if (i < N_NODES) g_rinv[i] = 1.0f / fmaxf(g_deg[i], 1.0f);
}

// ------------- SGEMM: C = (A * rowscale) @ W + b, N=K=128 fixed -----------
// 128x128 tile per block, BK=32, 256 threads, 8x8 micro-tile per thread.
#define BK 32
__global__ __launch_bounds__(256) void gemm128_kernel(
    const float* __restrict__ A, const float* __restrict__ rowscale,
    const float* __restrict__ W, const float* __restrict__ bias,
    float* __restrict__ C, int nrows) {
    __shared__ float As[BK][129];   // transposed A tile, padded
    __shared__ float Ws[BK][DIM];

    int tid = threadIdx.x;
    int ty = tid >> 4;        // 0..15
    int tx = tid & 15;        // 0..15
    int rowBase = blockIdx.x * 128;

    float acc[8][8];
#pragma unroll
    for (int i = 0; i < 8; i++)
#pragma unroll
        for (int j = 0; j < 8; j++) acc[i][j] = 0.0f;

    for (int kb = 0; kb < DIM; kb += BK) {
#pragma unroll
        for (int it = 0; it < 4; it++) {
            int idx = tid + it * 256;            // 0..1023
            // ---- A tile: 128 rows x 32 k  (8 float4 per row) ----
            int ar = idx >> 3;                   // 0..127
            int ak = (idx & 7) * 4;              // 0,4,...,28
            int grow = rowBase + ar;
            float4 v = make_float4(0.f, 0.f, 0.f, 0.f);
            float sc = 1.0f;
            if (grow < nrows) {
                v = *(const float4*)&A[(long long)grow * DIM + kb + ak];
                if (rowscale) sc = rowscale[grow];
            }
            As[ak + 0][ar] = v.x * sc;
            As[ak + 1][ar] = v.y * sc;
            As[ak + 2][ar] = v.z * sc;
            As[ak + 3][ar] = v.w * sc;
            // ---- W tile: 32 k x 128 cols (32 float4 per k-row) ----
            int wr = idx >> 5;                   // 0..31
            int wc = (idx & 31) * 4;             // 0..124
            *(float4*)&Ws[wr][wc] = *(const float4*)&W[(long long)(kb + wr) * DIM + wc];
        }
        __syncthreads();

#pragma unroll
        for (int k = 0; k < BK; k++) {
            float a[8], b[8];
#pragma unroll
            for (int i = 0; i < 8; i++) a[i] = As[k][ty * 8 + i];
            float4 b0 = *(const float4*)&Ws[k][tx * 8];
            float4 b1 = *(const float4*)&Ws[k][tx * 8 + 4];
            b[0] = b0.x; b[1] = b0.y; b[2] = b0.z; b[3] = b0.w;
            b[4] = b1.x; b[5] = b1.y; b[6] = b1.z; b[7] = b1.w;
#pragma unroll
            for (int i = 0; i < 8; i++)
#pragma unroll
                for (int j = 0; j < 8; j++) acc[i][j] += a[i] * b[j];
        }
        __syncthreads();
    }

    float bi[8];
#pragma unroll
    for (int j = 0; j < 8; j++) bi[j] = bias[tx * 8 + j];
#pragma unroll
    for (int i = 0; i < 8; i++) {
        int row = rowBase + ty * 8 + i;
        if (row < nrows) {
#pragma unroll
            for (int j = 0; j < 8; j += 4) {
                float4 o;
                o.x = acc[i][j + 0] + bi[j + 0];
                o.y = acc[i][j + 1] + bi[j + 1];
                o.z = acc[i][j + 2] + bi[j + 2];
                o.w = acc[i][j + 3] + bi[j + 3];
                *(float4*)&C[(long long)row * DIM + tx * 8 + j] = o;
            }
        }
    }
}

// ------------- pass 2: per-edge score + denom (warp/edge) -----------------
__global__ void edge_score_kernel(const int* __restrict__ src,
                                  const int* __restrict__ dst,
                                  const float* __restrict__ att_w,
                                  const float* __restrict__ att_b) {
    int gtid = blockIdx.x * blockDim.x + threadIdx.x;
    int e = gtid >> 5;
    int lane = threadIdx.x & 31;
    if (e >= N_EDGES) return;
    int s = src[e];
    int d = dst[e];
    float4 a = *(const float4*)&g_ha_src[(long long)s * DIM + lane * 4];
    float4 b = *(const float4*)&g_ha_dst[(long long)d * DIM + lane * 4];
    float4 w = *(const float4*)&att_w[lane * 4];

    float t;
    {
        float v0 = a.x + b.x, v1 = a.y + b.y, v2 = a.z + b.z, v3 = a.w + b.w;
        v0 = (v0 >= 0.f) ? v0 : v0 * NEG_SLOPE;
        v1 = (v1 >= 0.f) ? v1 : v1 * NEG_SLOPE;
        v2 = (v2 >= 0.f) ? v2 : v2 * NEG_SLOPE;
        v3 = (v3 >= 0.f) ? v3 : v3 * NEG_SLOPE;
        t = v0 * w.x + v1 * w.y + v2 * w.z + v3 * w.w;
    }
#pragma unroll
    for (int off = 16; off > 0; off >>= 1)
        t += __shfl_xor_sync(0xFFFFFFFFu, t, off);
    if (lane == 0) {
        float sv = expf(t + att_b[0]);
        g_s[e] = sv;
        atomicAdd(&g_denom[d], sv);
    }
}

// ------------- pass 3: out[dst] += x[src] * a (warp/edge) -----------------
__global__ void edge_out_kernel(const float* __restrict__ x,
                                const int* __restrict__ src,
                                const int* __restrict__ dst,
                                float* __restrict__ out) {
    int gtid = blockIdx.x * blockDim.x + threadIdx.x;
    int e = gtid >> 5;
    int lane = threadIdx.x & 31;
    if (e >= N_EDGES) return;
    int s = src[e];
    int d = dst[e];
    float a = g_s[e] / g_denom[d];
    float4 v = *(const float4*)&x[(long long)s * DIM + lane * 4];
    float* op = &out[(long long)d * DIM + lane * 4];
    atomicAdd(op + 0, v.x * a);
    atomicAdd(op + 1, v.y * a);
    atomicAdd(op + 2, v.z * a);
    atomicAdd(op + 3, v.w * a);
}

// ---------------------------------------------------------------------------
extern "C" void kernel_launch(void* const* d_in, const int* in_sizes, int n_in,
                              void* d_out, int out_size) {
    const float* x       = (const float*)d_in[0];
    const int*   src_idx = (const int*)d_in[1];
    const int*   dst_idx = (const int*)d_in[2];
    const float* src_w   = (const float*)d_in[3];
    const float* src_b   = (const float*)d_in[4];
    const float* dst_w   = (const float*)d_in[5];
    const float* dst_b   = (const float*)d_in[6];
    const float* att_w   = (const float*)d_in[7];
    const float* att_b   = (const float*)d_in[8];
    float* out = (float*)d_out;

    (void)in_sizes; (void)n_in; (void)out_size;

    float *hsum_p, *rinv_p, *ha_src_p, *ha_dst_p;
    cudaGetSymbolAddress((void**)&hsum_p,   g_hsum);
    cudaGetSymbolAddress((void**)&rinv_p,   g_rinv);
    cudaGetSymbolAddress((void**)&ha_src_p, g_ha_src);
    cudaGetSymbolAddress((void**)&ha_dst_p, g_ha_dst);

    const int edgeBlocks = (N_EDGES * 32 + 255) / 256;

    zero_kernel<<<2048, 256>>>(out);

    edge_agg_kernel<<<edgeBlocks, 256>>>(x, src_idx, dst_idx);

    rinv_kernel<<<(N_NODES + 255) / 256, 256>>>();

    int gemmBlocks = (N_NODES + 127) / 128;
    gemm128_kernel<<<gemmBlocks, 256>>>(x, nullptr, src_w, src_b, ha_src_p, N_NODES);
    gemm128_kernel<<<gemmBlocks, 256>>>(hsum_p, rinv_p, dst_w, dst_b, ha_dst_p, N_NODES);

    edge_score_kernel<<<edgeBlocks, 256>>>(src_idx, dst_idx, att_w, att_b);

    edge_out_kernel<<<edgeBlocks, 256>>>(x, src_idx, dst_idx, out);
}

// round 2
// speedup vs baseline: 2.1895x; 2.1895x over previous
#include <cuda_runtime.h>
#include <cuda_bf16.h>

#define N_NODES 50000
#define N_EDGES 800000
#define DIM 128
#define NEG_SLOPE 0.01f

// ---------------- scratch (device globals; no allocation allowed) ----------
__device__ int   g_cnt[N_NODES];
__device__ int   g_off[N_NODES + 1];
__device__ int   g_cur[N_NODES];
__device__ int   g_ssrc[N_EDGES];
__device__ float g_hmean[N_NODES * DIM];
__device__ float g_ha_src[N_NODES * DIM];
__device__ float g_ha_dst[N_NODES * DIM];
__device__ float g_s[N_EDGES];

// ---------------- k0: zero histogram counters ------------------------------
__global__ void zero_cnt_kernel() {
    int i = blockIdx.x * blockDim.x + threadIdx.x;
    if (i < N_NODES) g_cnt[i] = 0;
}

// ---------------- k1: degree histogram over dst ----------------------------
__global__ void hist_kernel(const int* __restrict__ dst) {
    int e = blockIdx.x * blockDim.x + threadIdx.x;
    if (e < N_EDGES) atomicAdd(&g_cnt[dst[e]], 1);
}

// ---------------- k2: single-block exclusive scan --> offsets + cursors ----
__global__ __launch_bounds__(1024) void scan_kernel() {
    __shared__ int sums[1024];
    int tid = threadIdx.x;
    const int chunk = (N_NODES + 1023) / 1024;
    int beg = tid * chunk;
    int end = min(beg + chunk, N_NODES);
    int s = 0;
    for (int i = beg; i < end; i++) s += g_cnt[i];
    sums[tid] = s;
    __syncthreads();
    // Hillis-Steele inclusive scan
    for (int off = 1; off < 1024; off <<= 1) {
        int t = (tid >= off) ? sums[tid - off] : 0;
        __syncthreads();
        sums[tid] += t;
        __syncthreads();
    }
    int run = sums[tid] - s;   // exclusive prefix of this thread's chunk
    for (int i = beg; i < end; i++) {
        g_off[i] = run;
        g_cur[i] = run;
        run += g_cnt[i];
    }
    if (tid == 0) g_off[N_NODES] = N_EDGES;
}

// ---------------- k3: scatter edges into dst-sorted order ------------------
__global__ void scatter_kernel(const int* __restrict__ src,
                               const int* __restrict__ dst) {
    int e = blockIdx.x * blockDim.x + threadIdx.x;
    if (e >= N_EDGES) return;
    int d = dst[e];
    int p = atomicAdd(&g_cur[d], 1);
    g_ssrc[p] = src[e];
}

// ---------------- k4: mean aggregation, warp per dst node ------------------
__global__ __launch_bounds__(256) void agg_kernel(const float* __restrict__ x) {
    int warp = (blockIdx.x * blockDim.x + threadIdx.x) >> 5;
    int lane = threadIdx.x & 31;
    if (warp >= N_NODES) return;
    int beg = g_off[warp];
    int end = g_off[warp + 1];
    float4 acc = make_float4(0.f, 0.f, 0.f, 0.f);
    int p = beg;
    for (; p + 3 < end; p += 4) {
        int s0 = g_ssrc[p], s1 = g_ssrc[p + 1], s2 = g_ssrc[p + 2], s3 = g_ssrc[p + 3];
        float4 v0 = *(const float4*)&x[(long long)s0 * DIM + lane * 4];
        float4 v1 = *(const float4*)&x[(long long)s1 * DIM + lane * 4];
        float4 v2 = *(const float4*)&x[(long long)s2 * DIM + lane * 4];
        float4 v3 = *(const float4*)&x[(long long)s3 * DIM + lane * 4];
        acc.x += v0.x + v1.x + v2.x + v3.x;
        acc.y += v0.y + v1.y + v2.y + v3.y;
        acc.z += v0.z + v1.z + v2.z + v3.z;
        acc.w += v0.w + v1.w + v2.w + v3.w;
    }
    for (; p < end; p++) {
        int s = g_ssrc[p];
        float4 v = *(const float4*)&x[(long long)s * DIM + lane * 4];
        acc.x += v.x; acc.y += v.y; acc.z += v.z; acc.w += v.w;
    }
    float r = 1.0f / (float)max(end - beg, 1);
    float4 o = make_float4(acc.x * r, acc.y * r, acc.z * r, acc.w * r);
    *(float4*)&g_hmean[(long long)warp * DIM + lane * 4] = o;
}

// ---------------- SGEMM: C = A @ W + b, N=K=128 fixed ----------------------
#define BK 32
__global__ __launch_bounds__(256) void gemm128_kernel(
    const float* __restrict__ A,
    const float* __restrict__ W, const float* __restrict__ bias,
    float* __restrict__ C, int nrows) {
    __shared__ float As[BK][129];
    __shared__ float Ws[BK][DIM];

    int tid = threadIdx.x;
    int ty = tid >> 4;
    int tx = tid & 15;
    int rowBase = blockIdx.x * 128;

    float acc[8][8];
#pragma unroll
    for (int i = 0; i < 8; i++)
#pragma unroll
        for (int j = 0; j < 8; j++) acc[i][j] = 0.0f;

    for (int kb = 0; kb < DIM; kb += BK) {
#pragma unroll
        for (int it = 0; it < 4; it++) {
            int idx = tid + it * 256;
            int ar = idx >> 3;
            int ak = (idx & 7) * 4;
            int grow = rowBase + ar;
            float4 v = make_float4(0.f, 0.f, 0.f, 0.f);
            if (grow < nrows)
                v = *(const float4*)&A[(long long)grow * DIM + kb + ak];
            As[ak + 0][ar] = v.x;
            As[ak + 1][ar] = v.y;
            As[ak + 2][ar] = v.z;
            As[ak + 3][ar] = v.w;
            int wr = idx >> 5;
            int wc = (idx & 31) * 4;
            *(float4*)&Ws[wr][wc] = *(const float4*)&W[(long long)(kb + wr) * DIM + wc];
        }
        __syncthreads();

#pragma unroll
        for (int k = 0; k < BK; k++) {
            float a[8], b[8];
#pragma unroll
            for (int i = 0; i < 8; i++) a[i] = As[k][ty * 8 + i];
            float4 b0 = *(const float4*)&Ws[k][tx * 8];
            float4 b1 = *(const float4*)&Ws[k][tx * 8 + 4];
            b[0] = b0.x; b[1] = b0.y; b[2] = b0.z; b[3] = b0.w;
            b[4] = b1.x; b[5] = b1.y; b[6] = b1.z; b[7] = b1.w;
#pragma unroll
            for (int i = 0; i < 8; i++)
#pragma unroll
                for (int j = 0; j < 8; j++) acc[i][j] += a[i] * b[j];
        }
        __syncthreads();
    }

    float bi[8];
#pragma unroll
    for (int j = 0; j < 8; j++) bi[j] = bias[tx * 8 + j];
#pragma unroll
    for (int i = 0; i < 8; i++) {
        int row = rowBase + ty * 8 + i;
        if (row < nrows) {
#pragma unroll
            for (int j = 0; j < 8; j += 4) {
                float4 o;
                o.x = acc[i][j + 0] + bi[j + 0];
                o.y = acc[i][j + 1] + bi[j + 1];
                o.z = acc[i][j + 2] + bi[j + 2];
                o.w = acc[i][j + 3] + bi[j + 3];
                *(float4*)&C[(long long)row * DIM + tx * 8 + j] = o;
            }
        }
    }
}

// ------- k7: fused score + softmax denom + weighted output, warp/node ------
__global__ __launch_bounds__(256) void fused_out_kernel(
    const float* __restrict__ x,
    const float* __restrict__ att_w,
    const float* __restrict__ att_b,
    float* __restrict__ out) {
    int warp = (blockIdx.x * blockDim.x + threadIdx.x) >> 5;
    int lane = threadIdx.x & 31;
    if (warp >= N_NODES) return;
    int beg = g_off[warp];
    int end = g_off[warp + 1];

    float4 b = *(const float4*)&g_ha_dst[(long long)warp * DIM + lane * 4];
    float4 w = *(const float4*)&att_w[lane * 4];
    float  c = att_b[0];

    // ---- pass A: scores + denom ----
    float denom = 0.0f;
    int p = beg;
    for (; p + 1 < end; p += 2) {
        int s0 = g_ssrc[p], s1 = g_ssrc[p + 1];
        float4 a0 = *(const float4*)&g_ha_src[(long long)s0 * DIM + lane * 4];
        float4 a1 = *(const float4*)&g_ha_src[(long long)s1 * DIM + lane * 4];
        float t0, t1;
        {
            float v0 = a0.x + b.x, v1 = a0.y + b.y, v2 = a0.z + b.z, v3 = a0.w + b.w;
            v0 = (v0 >= 0.f) ? v0 : v0 * NEG_SLOPE;
            v1 = (v1 >= 0.f) ? v1 : v1 * NEG_SLOPE;
            v2 = (v2 >= 0.f) ? v2 : v2 * NEG_SLOPE;
            v3 = (v3 >= 0.f) ? v3 : v3 * NEG_SLOPE;
            t0 = v0 * w.x + v1 * w.y + v2 * w.z + v3 * w.w;
        }
        {
            float v0 = a1.x + b.x, v1 = a1.y + b.y, v2 = a1.z + b.z, v3 = a1.w + b.w;
            v0 = (v0 >= 0.f) ? v0 : v0 * NEG_SLOPE;
            v1 = (v1 >= 0.f) ? v1 : v1 * NEG_SLOPE;
            v2 = (v2 >= 0.f) ? v2 : v2 * NEG_SLOPE;
            v3 = (v3 >= 0.f) ? v3 : v3 * NEG_SLOPE;
            t1 = v0 * w.x + v1 * w.y + v2 * w.z + v3 * w.w;
        }
#pragma unroll
        for (int off = 16; off > 0; off >>= 1) {
            t0 += __shfl_xor_sync(0xFFFFFFFFu, t0, off);
            t1 += __shfl_xor_sync(0xFFFFFFFFu, t1, off);
        }
        float sv0 = expf(t0 + c);
        float sv1 = expf(t1 + c);
        denom += sv0 + sv1;
        if (lane == 0) { g_s[p] = sv0; g_s[p + 1] = sv1; }
    }
    for (; p < end; p++) {
        int s = g_ssrc[p];
        float4 a = *(const float4*)&g_ha_src[(long long)s * DIM + lane * 4];
        float v0 = a.x + b.x, v1 = a.y + b.y, v2 = a.z + b.z, v3 = a.w + b.w;
        v0 = (v0 >= 0.f) ? v0 : v0 * NEG_SLOPE;
        v1 = (v1 >= 0.f) ? v1 : v1 * NEG_SLOPE;
        v2 = (v2 >= 0.f) ? v2 : v2 * NEG_SLOPE;
        v3 = (v3 >= 0.f) ? v3 : v3 * NEG_SLOPE;
        float t = v0 * w.x + v1 * w.y + v2 * w.z + v3 * w.w;
#pragma unroll
        for (int off = 16; off > 0; off >>= 1)
            t += __shfl_xor_sync(0xFFFFFFFFu, t, off);
        float sv = expf(t + c);
        denom += sv;
        if (lane == 0) g_s[p] = sv;
    }

    float rd = 1.0f / denom;   // unused (and inf-safe) when end==beg

    // ---- pass B: weighted aggregation ----
    float4 o = make_float4(0.f, 0.f, 0.f, 0.f);
    p = beg;
    for (; p + 1 < end; p += 2) {
        int s0 = g_ssrc[p], s1 = g_ssrc[p + 1];
        float a0 = g_s[p] * rd;
        float a1 = g_s[p + 1] * rd;
        float4 v0 = *(const float4*)&x[(long long)s0 * DIM + lane * 4];
        float4 v1 = *(const float4*)&x[(long long)s1 * DIM + lane * 4];
        o.x += v0.x * a0 + v1.x * a1;
        o.y += v0.y * a0 + v1.y * a1;
        o.z += v0.z * a0 + v1.z * a1;
        o.w += v0.w * a0 + v1.w * a1;
    }
    for (; p < end; p++) {
        int s = g_ssrc[p];
        float a = g_s[p] * rd;
        float4 v = *(const float4*)&x[(long long)s * DIM + lane * 4];
        o.x += v.x * a; o.y += v.y * a; o.z += v.z * a; o.w += v.w * a;
    }
    *(float4*)&out[(long long)warp * DIM + lane * 4] = o;
}

// ---------------------------------------------------------------------------
extern "C" void kernel_launch(void* const* d_in, const int* in_sizes, int n_in,
                              void* d_out, int out_size) {
    const float* x       = (const float*)d_in[0];
    const int*   src_idx = (const int*)d_in[1];
    const int*   dst_idx = (const int*)d_in[2];
    const float* src_w   = (const float*)d_in[3];
    const float* src_b   = (const float*)d_in[4];
    const float* dst_w   = (const float*)d_in[5];
    const float* dst_b   = (const float*)d_in[6];
    const float* att_w   = (const float*)d_in[7];
    const float* att_b   = (const float*)d_in[8];
    float* out = (float*)d_out;

    (void)in_sizes; (void)n_in; (void)out_size;

    float *hmean_p, *ha_src_p, *ha_dst_p;
    cudaGetSymbolAddress((void**)&hmean_p,  g_hmean);
    cudaGetSymbolAddress((void**)&ha_src_p, g_ha_src);
    cudaGetSymbolAddress((void**)&ha_dst_p, g_ha_dst);

    const int eThreads = (N_EDGES + 255) / 256;
    const int nodeWarpBlocks = (N_NODES * 32 + 255) / 256;

    zero_cnt_kernel<<<(N_NODES + 255) / 256, 256>>>();
    hist_kernel<<<eThreads, 256>>>(dst_idx);
    scan_kernel<<<1, 1024>>>();
    scatter_kernel<<<eThreads, 256>>>(src_idx, dst_idx);

    agg_kernel<<<nodeWarpBlocks, 256>>>(x);

    int gemmBlocks = (N_NODES + 127) / 128;
    gemm128_kernel<<<gemmBlocks, 256>>>(x,       src_w, src_b, ha_src_p, N_NODES);
    gemm128_kernel<<<gemmBlocks, 256>>>(hmean_p, dst_w, dst_b, ha_dst_p, N_NODES);

    fused_out_kernel<<<nodeWarpBlocks, 256>>>(x, att_w, att_b, out);
}

// round 4
// speedup vs baseline: 3.0234x; 1.3809x over previous
#include <cuda_runtime.h>
#include <cuda_bf16.h>
#include <cstdint>

#define N_NODES 50000
#define N_EDGES 800000
#define DIM 128
#define NEG_SLOPE 0.01f

#define SCAN_BLK 1024
#define SCAN_NBLK ((N_NODES + SCAN_BLK - 1) / SCAN_BLK)   // 49

// ---------------- scratch (device globals; no allocation allowed) ----------
__device__ int   g_cnt[N_NODES];
__device__ int   g_off[N_NODES + 1];
__device__ int   g_cur[N_NODES];
__device__ int   g_part[64];
__device__ int   g_ssrc[N_EDGES];
__device__ float g_hmean[N_NODES * DIM];
__device__ float g_ha_src[N_NODES * DIM];
__device__ float g_ha_dst[N_NODES * DIM];
__device__ float g_s[N_EDGES];

// ---------------- k0: zero histogram counters ------------------------------
__global__ void zero_cnt_kernel() {
    int i = blockIdx.x * blockDim.x + threadIdx.x;
    if (i < N_NODES) g_cnt[i] = 0;
}

// ---------------- k1: degree histogram over dst ----------------------------
__global__ void hist_kernel(const int* __restrict__ dst) {
    int e = blockIdx.x * blockDim.x + threadIdx.x;
    if (e < N_EDGES) atomicAdd(&g_cnt[dst[e]], 1);
}

// ---------------- k2a: per-block sums --------------------------------------
__global__ __launch_bounds__(SCAN_BLK) void scan_a_kernel() {
    __shared__ int sh[SCAN_BLK];
    int tid = threadIdx.x;
    int i = blockIdx.x * SCAN_BLK + tid;
    sh[tid] = (i < N_NODES) ? g_cnt[i] : 0;
    __syncthreads();
    for (int off = SCAN_BLK / 2; off > 0; off >>= 1) {
        if (tid < off) sh[tid] += sh[tid + off];
        __syncthreads();
    }
    if (tid == 0) g_part[blockIdx.x] = sh[0];
}

// ---------------- k2b: scan the 49 partials (exclusive) --------------------
__global__ void scan_b_kernel() {
    __shared__ int sh[64];
    int tid = threadIdx.x;
    int v = (tid < SCAN_NBLK) ? g_part[tid] : 0;
    sh[tid] = v;
    __syncthreads();
    for (int off = 1; off < 64; off <<= 1) {
        int t = (tid >= off) ? sh[tid - off] : 0;
        __syncthreads();
        sh[tid] += t;
        __syncthreads();
    }
    if (tid < SCAN_NBLK) g_part[tid] = sh[tid] - v;   // exclusive
}

// ---------------- k2c: block-local scan + offset -> g_off, g_cur -----------
__global__ __launch_bounds__(SCAN_BLK) void scan_c_kernel() {
    __shared__ int sh[SCAN_BLK];
    int tid = threadIdx.x;
    int i = blockIdx.x * SCAN_BLK + tid;
    int v = (i < N_NODES) ? g_cnt[i] : 0;
    sh[tid] = v;
    __syncthreads();
    for (int off = 1; off < SCAN_BLK; off <<= 1) {
        int t = (tid >= off) ? sh[tid - off] : 0;
        __syncthreads();
        sh[tid] += t;
        __syncthreads();
    }
    int excl = sh[tid] - v + g_part[blockIdx.x];
    if (i < N_NODES) {
        g_off[i] = excl;
        g_cur[i] = excl;
    }
    if (i == 0) g_off[N_NODES] = N_EDGES;
}

// ---------------- k3: scatter edges into dst-sorted order ------------------
__global__ void scatter_kernel(const int* __restrict__ src,
                               const int* __restrict__ dst) {
    int e = blockIdx.x * blockDim.x + threadIdx.x;
    if (e >= N_EDGES) return;
    int d = dst[e];
    int p = atomicAdd(&g_cur[d], 1);
    g_ssrc[p] = src[e];
}

// ---------------- k4: mean aggregation, warp per dst node ------------------
__global__ __launch_bounds__(256) void agg_kernel(const float* __restrict__ x) {
    int warp = (blockIdx.x * blockDim.x + threadIdx.x) >> 5;
    int lane = threadIdx.x & 31;
    if (warp >= N_NODES) return;
    int beg = g_off[warp];
    int end = g_off[warp + 1];
    float4 acc = make_float4(0.f, 0.f, 0.f, 0.f);
    int p = beg;
    for (; p + 3 < end; p += 4) {
        int s0 = g_ssrc[p], s1 = g_ssrc[p + 1], s2 = g_ssrc[p + 2], s3 = g_ssrc[p + 3];
        float4 v0 = *(const float4*)&x[(long long)s0 * DIM + lane * 4];
        float4 v1 = *(const float4*)&x[(long long)s1 * DIM + lane * 4];
        float4 v2 = *(const float4*)&x[(long long)s2 * DIM + lane * 4];
        float4 v3 = *(const float4*)&x[(long long)s3 * DIM + lane * 4];
        acc.x += v0.x + v1.x + v2.x + v3.x;
        acc.y += v0.y + v1.y + v2.y + v3.y;
        acc.z += v0.z + v1.z + v2.z + v3.z;
        acc.w += v0.w + v1.w + v2.w + v3.w;
    }
    for (; p < end; p++) {
        int s = g_ssrc[p];
        float4 v = *(const float4*)&x[(long long)s * DIM + lane * 4];
        acc.x += v.x; acc.y += v.y; acc.z += v.z; acc.w += v.w;
    }
    float r = 1.0f / (float)max(end - beg, 1);
    float4 o = make_float4(acc.x * r, acc.y * r, acc.z * r, acc.w * r);
    *(float4*)&g_hmean[(long long)warp * DIM + lane * 4] = o;
}

// ---------------- tf32x3 tensor-core GEMM ----------------------------------
// C[M,128] = A[M,128] @ W[128,128] + bias, near-fp32 precision via hi/lo split.
// Block: 128 rows, full N=128, full K=128 staged in smem. 256 threads, 8 warps
// as 4(M)x2(N); warp tile 32x64; mma.m16n8k8.

__device__ __forceinline__ uint32_t f2tf(float f) {
    uint32_t u;
    asm("cvt.rna.tf32.f32 %0, %1;" : "=r"(u) : "f"(f));
    return u;
}

__device__ __forceinline__ void mma_tf32(float* c, const uint32_t* a, const uint32_t* b) {
    asm volatile(
        "mma.sync.aligned.m16n8k8.row.col.f32.tf32.tf32.f32 "
        "{%0,%1,%2,%3}, {%4,%5,%6,%7}, {%8,%9}, {%0,%1,%2,%3};"
        : "+f"(c[0]), "+f"(c[1]), "+f"(c[2]), "+f"(c[3])
        : "r"(a[0]), "r"(a[1]), "r"(a[2]), "r"(a[3]), "r"(b[0]), "r"(b[1]));
}

#define SMSTRIDE 132
#define GEMM_SMEM (2 * 128 * SMSTRIDE * 4)

__global__ __launch_bounds__(256) void gemm_tc_kernel(
    const float* __restrict__ x, const float* __restrict__ hmean,
    const float* __restrict__ src_w, const float* __restrict__ dst_w,
    const float* __restrict__ src_b, const float* __restrict__ dst_b,
    float* __restrict__ ha_src, float* __restrict__ ha_dst) {
    extern __shared__ float sm[];
    float* As = sm;                      // 128 x SMSTRIDE
    float* Ws = sm + 128 * SMSTRIDE;     // 128 x SMSTRIDE (row = k)

    const float* A    = (blockIdx.y == 0) ? x     : hmean;
    const float* W    = (blockIdx.y == 0) ? src_w : dst_w;
    const float* bias = (blockIdx.y == 0) ? src_b : dst_b;
    float*       C    = (blockIdx.y == 0) ? ha_src : ha_dst;

    int tid = threadIdx.x;
    int rowBase = blockIdx.x * 128;

    // stage A tile and full W into smem (float4, 16 iters each thread)
#pragma unroll
    for (int it = 0; it < 16; it++) {
        int idx = tid + it * 256;            // 0..4095 float4 slots
        int r = idx >> 5;                    // 0..127
        int c = (idx & 31) * 4;              // 0..124
        float4 v = make_float4(0.f, 0.f, 0.f, 0.f);
        if (rowBase + r < N_NODES)
            v = *(const float4*)&A[(long long)(rowBase + r) * DIM + c];
        *(float4*)&As[r * SMSTRIDE + c] = v;
        float4 wv = *(const float4*)&W[(long long)r * DIM + c];
        *(float4*)&Ws[r * SMSTRIDE + c] = wv;
    }
    __syncthreads();

    int wid = tid >> 5, lane = tid & 31;
    int g = lane >> 2, t = lane & 3;
    int warpM = wid & 3, warpN = wid >> 2;
    int wrow = warpM * 32, wcol = warpN * 64;

    float acc[2][8][4];
#pragma unroll
    for (int mt = 0; mt < 2; mt++)
#pragma unroll
        for (int nt = 0; nt < 8; nt++)
#pragma unroll
            for (int j = 0; j < 4; j++) acc[mt][nt][j] = 0.0f;

    for (int kt = 0; kt < 16; kt++) {
        int k0 = kt * 8;
        uint32_t ahi[2][4], alo[2][4];
#pragma unroll
        for (int mt = 0; mt < 2; mt++) {
            int r0 = wrow + mt * 16;
            float a0 = As[(r0 + g) * SMSTRIDE + k0 + t];
            float a1 = As[(r0 + g + 8) * SMSTRIDE + k0 + t];
            float a2 = As[(r0 + g) * SMSTRIDE + k0 + t + 4];
            float a3 = As[(r0 + g + 8) * SMSTRIDE + k0 + t + 4];
            ahi[mt][0] = f2tf(a0); alo[mt][0] = f2tf(a0 - __uint_as_float(ahi[mt][0]));
            ahi[mt][1] = f2tf(a1); alo[mt][1] = f2tf(a1 - __uint_as_float(ahi[mt][1]));
            ahi[mt][2] = f2tf(a2); alo[mt][2] = f2tf(a2 - __uint_as_float(ahi[mt][2]));
            ahi[mt][3] = f2tf(a3); alo[mt][3] = f2tf(a3 - __uint_as_float(ahi[mt][3]));
        }
        uint32_t bhi[8][2], blo[8][2];
#pragma unroll
        for (int nt = 0; nt < 8; nt++) {
            int col = wcol + nt * 8 + g;
            float b0 = Ws[(k0 + t) * SMSTRIDE + col];
            float b1 = Ws[(k0 + t + 4) * SMSTRIDE + col];
            bhi[nt][0] = f2tf(b0); blo[nt][0] = f2tf(b0 - __uint_as_float(bhi[nt][0]));
            bhi[nt][1] = f2tf(b1); blo[nt][1] = f2tf(b1 - __uint_as_float(bhi[nt][1]));
        }
#pragma unroll
        for (int mt = 0; mt < 2; mt++)
#pragma unroll
            for (int nt = 0; nt < 8; nt++) {
                mma_tf32(acc[mt][nt], ahi[mt], blo[nt]);
                mma_tf32(acc[mt][nt], alo[mt], bhi[nt]);
                mma_tf32(acc[mt][nt], ahi[mt], bhi[nt]);
            }
    }

    // epilogue
#pragma unroll
    for (int mt = 0; mt < 2; mt++) {
#pragma unroll
        for (int nt = 0; nt < 8; nt++) {
            int col = wcol + nt * 8 + 2 * t;
            float b0 = bias[col], b1 = bias[col + 1];
            int row0 = rowBase + wrow + mt * 16 + g;
            int row1 = row0 + 8;
            if (row0 < N_NODES) {
                float2 o0 = make_float2(acc[mt][nt][0] + b0, acc[mt][nt][1] + b1);
                *(float2*)&C[(long long)row0 * DIM + col] = o0;
            }
            if (row1 < N_NODES) {
                float2 o1 = make_float2(acc[mt][nt][2] + b0, acc[mt][nt][3] + b1);
                *(float2*)&C[(long long)row1 * DIM + col] = o1;
            }
        }
    }
}

// ------- k7: fused score + softmax denom + weighted output, warp/node ------
__global__ __launch_bounds__(256) void fused_out_kernel(
    const float* __restrict__ x,
    const float* __restrict__ att_w,
    const float* __restrict__ att_b,
    float* __restrict__ out) {
    int warp = (blockIdx.x * blockDim.x + threadIdx.x) >> 5;
    int lane = threadIdx.x & 31;
    if (warp >= N_NODES) return;
    int beg = g_off[warp];
    int end = g_off[warp + 1];

    float4 b = *(const float4*)&g_ha_dst[(long long)warp * DIM + lane * 4];
    float4 w = *(const float4*)&att_w[lane * 4];
    float  c = att_b[0];

    float denom = 0.0f;
    int p = beg;
    for (; p + 1 < end; p += 2) {
        int s0 = g_ssrc[p], s1 = g_ssrc[p + 1];
        float4 a0 = *(const float4*)&g_ha_src[(long long)s0 * DIM + lane * 4];
        float4 a1 = *(const float4*)&g_ha_src[(long long)s1 * DIM + lane * 4];
        float t0, t1;
        {
            float v0 = a0.x + b.x, v1 = a0.y + b.y, v2 = a0.z + b.z, v3 = a0.w + b.w;
            v0 = (v0 >= 0.f) ? v0 : v0 * NEG_SLOPE;
            v1 = (v1 >= 0.f) ? v1 : v1 * NEG_SLOPE;
            v2 = (v2 >= 0.f) ? v2 : v2 * NEG_SLOPE;
            v3 = (v3 >= 0.f) ? v3 : v3 * NEG_SLOPE;
            t0 = v0 * w.x + v1 * w.y + v2 * w.z + v3 * w.w;
        }
        {
            float v0 = a1.x + b.x, v1 = a1.y + b.y, v2 = a1.z + b.z, v3 = a1.w + b.w;
            v0 = (v0 >= 0.f) ? v0 : v0 * NEG_SLOPE;
            v1 = (v1 >= 0.f) ? v1 : v1 * NEG_SLOPE;
            v2 = (v2 >= 0.f) ? v2 : v2 * NEG_SLOPE;
            v3 = (v3 >= 0.f) ? v3 : v3 * NEG_SLOPE;
            t1 = v0 * w.x + v1 * w.y + v2 * w.z + v3 * w.w;
        }
#pragma unroll
        for (int off = 16; off > 0; off >>= 1) {
            t0 += __shfl_xor_sync(0xFFFFFFFFu, t0, off);
            t1 += __shfl_xor_sync(0xFFFFFFFFu, t1, off);
        }
        float sv0 = expf(t0 + c);
        float sv1 = expf(t1 + c);
        denom += sv0 + sv1;
        if (lane == 0) { g_s[p] = sv0; g_s[p + 1] = sv1; }
    }
    for (; p < end; p++) {
        int s = g_ssrc[p];
        float4 a = *(const float4*)&g_ha_src[(long long)s * DIM + lane * 4];
        float v0 = a.x + b.x, v1 = a.y + b.y, v2 = a.z + b.z, v3 = a.w + b.w;
        v0 = (v0 >= 0.f) ? v0 : v0 * NEG_SLOPE;
        v1 = (v1 >= 0.f) ? v1 : v1 * NEG_SLOPE;
        v2 = (v2 >= 0.f) ? v2 : v2 * NEG_SLOPE;
        v3 = (v3 >= 0.f) ? v3 : v3 * NEG_SLOPE;
        float t = v0 * w.x + v1 * w.y + v2 * w.z + v3 * w.w;
#pragma unroll
        for (int off = 16; off > 0; off >>= 1)
            t += __shfl_xor_sync(0xFFFFFFFFu, t, off);
        float sv = expf(t + c);
        denom += sv;
        if (lane == 0) g_s[p] = sv;
    }

    float rd = 1.0f / denom;

    float4 o = make_float4(0.f, 0.f, 0.f, 0.f);
    p = beg;
    for (; p + 1 < end; p += 2) {
        int s0 = g_ssrc[p], s1 = g_ssrc[p + 1];
        float a0 = g_s[p] * rd;
        float a1 = g_s[p + 1] * rd;
        float4 v0 = *(const float4*)&x[(long long)s0 * DIM + lane * 4];
        float4 v1 = *(const float4*)&x[(long long)s1 * DIM + lane * 4];
        o.x += v0.x * a0 + v1.x * a1;
        o.y += v0.y * a0 + v1.y * a1;
        o.z += v0.z * a0 + v1.z * a1;
        o.w += v0.w * a0 + v1.w * a1;
    }
    for (; p < end; p++) {
        int s = g_ssrc[p];
        float a = g_s[p] * rd;
        float4 v = *(const float4*)&x[(long long)s * DIM + lane * 4];
        o.x += v.x * a; o.y += v.y * a; o.z += v.z * a; o.w += v.w * a;
    }
    *(float4*)&out[(long long)warp * DIM + lane * 4] = o;
}

// ---------------------------------------------------------------------------
extern "C" void kernel_launch(void* const* d_in, const int* in_sizes, int n_in,
                              void* d_out, int out_size) {
    const float* x       = (const float*)d_in[0];
    const int*   src_idx = (const int*)d_in[1];
    const int*   dst_idx = (const int*)d_in[2];
    const float* src_w   = (const float*)d_in[3];
    const float* src_b   = (const float*)d_in[4];
    const float* dst_w   = (const float*)d_in[5];
    const float* dst_b   = (const float*)d_in[6];
    const float* att_w   = (const float*)d_in[7];
    const float* att_b   = (const float*)d_in[8];
    float* out = (float*)d_out;

    (void)in_sizes; (void)n_in; (void)out_size;

    float *hmean_p, *ha_src_p, *ha_dst_p;
    cudaGetSymbolAddress((void**)&hmean_p,  g_hmean);
    cudaGetSymbolAddress((void**)&ha_src_p, g_ha_src);
    cudaGetSymbolAddress((void**)&ha_dst_p, g_ha_dst);

    cudaFuncSetAttribute(gemm_tc_kernel,
                         cudaFuncAttributeMaxDynamicSharedMemorySize, GEMM_SMEM);

    const int eBlocks = (N_EDGES + 255) / 256;
    const int nodeWarpBlocks = (N_NODES * 32 + 255) / 256;

    zero_cnt_kernel<<<(N_NODES + 255) / 256, 256>>>();
    hist_kernel<<<eBlocks, 256>>>(dst_idx);
    scan_a_kernel<<<SCAN_NBLK, SCAN_BLK>>>();
    scan_b_kernel<<<1, 64>>>();
    scan_c_kernel<<<SCAN_NBLK, SCAN_BLK>>>();
    scatter_kernel<<<eBlocks, 256>>>(src_idx, dst_idx);

    agg_kernel<<<nodeWarpBlocks, 256>>>(x);

    dim3 gemmGrid((N_NODES + 127) / 128, 2);
    gemm_tc_kernel<<<gemmGrid, 256, GEMM_SMEM>>>(
        x, hmean_p, src_w, dst_w, src_b, dst_b, ha_src_p, ha_dst_p);

    fused_out_kernel<<<nodeWarpBlocks, 256>>>(x, att_w, att_b, out);
}

// round 6
// speedup vs baseline: 3.3345x; 1.1029x over previous
#include <cuda_runtime.h>
#include <cuda_bf16.h>
#include <cstdint>

#define N_NODES 50000
#define N_EDGES 800000
#define DIM 128
#define NEG_SLOPE 0.01f

#define SCAN_BLK 1024
#define SCAN_NBLK ((N_NODES + SCAN_BLK - 1) / SCAN_BLK)   // 49

// ---------------- scratch (device globals; no allocation allowed) ----------
__device__ int   g_cnt[N_NODES];
__device__ int   g_off[N_NODES + 1];
__device__ int   g_cur[N_NODES];
__device__ int   g_part[64];
__device__ int   g_ssrc[N_EDGES];
__device__ float g_hmean[N_NODES * DIM];
__device__ float g_ha_src[N_NODES * DIM];
__device__ float g_ha_dst[N_NODES * DIM];

// ---------------- k0: zero histogram counters ------------------------------
__global__ void zero_cnt_kernel() {
    int i = blockIdx.x * blockDim.x + threadIdx.x;
    if (i < N_NODES) g_cnt[i] = 0;
}

// ---------------- k1: degree histogram over dst (ILP-4) --------------------
__global__ void hist_kernel(const int* __restrict__ dst) {
    int base = (blockIdx.x * blockDim.x + threadIdx.x) * 4;
    if (base + 3 < N_EDGES) {
        int4 d4 = *(const int4*)&dst[base];
        atomicAdd(&g_cnt[d4.x], 1);
        atomicAdd(&g_cnt[d4.y], 1);
        atomicAdd(&g_cnt[d4.z], 1);
        atomicAdd(&g_cnt[d4.w], 1);
    } else {
        for (int e = base; e < N_EDGES; e++) atomicAdd(&g_cnt[dst[e]], 1);
    }
}

// ---------------- k2a: per-block sums --------------------------------------
__global__ __launch_bounds__(SCAN_BLK) void scan_a_kernel() {
    __shared__ int sh[SCAN_BLK];
    int tid = threadIdx.x;
    int i = blockIdx.x * SCAN_BLK + tid;
    sh[tid] = (i < N_NODES) ? g_cnt[i] : 0;
    __syncthreads();
    for (int off = SCAN_BLK / 2; off > 0; off >>= 1) {
        if (tid < off) sh[tid] += sh[tid + off];
        __syncthreads();
    }
    if (tid == 0) g_part[blockIdx.x] = sh[0];
}

// ------- k2c: block-local scan + (redundant) partial scan -> offsets -------
__global__ __launch_bounds__(SCAN_BLK) void scan_c_kernel() {
    __shared__ int sh[SCAN_BLK];
    __shared__ int blockOff;
    int tid = threadIdx.x;
    int i = blockIdx.x * SCAN_BLK + tid;
    int v = (i < N_NODES) ? g_cnt[i] : 0;
    sh[tid] = v;
    if (tid == 0) {
        int s = 0;
        for (int b = 0; b < (int)blockIdx.x; b++) s += g_part[b];
        blockOff = s;
    }
    __syncthreads();
    for (int off = 1; off < SCAN_BLK; off <<= 1) {
        int t = (tid >= off) ? sh[tid - off] : 0;
        __syncthreads();
        sh[tid] += t;
        __syncthreads();
    }
    int excl = sh[tid] - v + blockOff;
    if (i < N_NODES) {
        g_off[i] = excl;
        g_cur[i] = excl;
    }
    if (i == 0) g_off[N_NODES] = N_EDGES;
}

// ---------------- k3: scatter edges into dst-sorted order (ILP-4) ----------
__global__ void scatter_kernel(const int* __restrict__ src,
                               const int* __restrict__ dst) {
    int base = (blockIdx.x * blockDim.x + threadIdx.x) * 4;
    if (base + 3 < N_EDGES) {
        int4 d4 = *(const int4*)&dst[base];
        int4 s4 = *(const int4*)&src[base];
        int p0 = atomicAdd(&g_cur[d4.x], 1);
        int p1 = atomicAdd(&g_cur[d4.y], 1);
        int p2 = atomicAdd(&g_cur[d4.z], 1);
        int p3 = atomicAdd(&g_cur[d4.w], 1);
        g_ssrc[p0] = s4.x;
        g_ssrc[p1] = s4.y;
        g_ssrc[p2] = s4.z;
        g_ssrc[p3] = s4.w;
    } else {
        for (int e = base; e < N_EDGES; e++) {
            int p = atomicAdd(&g_cur[dst[e]], 1);
            g_ssrc[p] = src[e];
        }
    }
}

// ---------------- k4: mean aggregation, warp per dst node ------------------
__global__ __launch_bounds__(256) void agg_kernel(const float* __restrict__ x) {
    int warp = (blockIdx.x * blockDim.x + threadIdx.x) >> 5;
    int lane = threadIdx.x & 31;
    if (warp >= N_NODES) return;
    int beg = g_off[warp];
    int end = g_off[warp + 1];
    float4 acc = make_float4(0.f, 0.f, 0.f, 0.f);
    int p = beg;
    for (; p + 3 < end; p += 4) {
        int s0 = g_ssrc[p], s1 = g_ssrc[p + 1], s2 = g_ssrc[p + 2], s3 = g_ssrc[p + 3];
        float4 v0 = *(const float4*)&x[(long long)s0 * DIM + lane * 4];
        float4 v1 = *(const float4*)&x[(long long)s1 * DIM + lane * 4];
        float4 v2 = *(const float4*)&x[(long long)s2 * DIM + lane * 4];
        float4 v3 = *(const float4*)&x[(long long)s3 * DIM + lane * 4];
        acc.x += v0.x + v1.x + v2.x + v3.x;
        acc.y += v0.y + v1.y + v2.y + v3.y;
        acc.z += v0.z + v1.z + v2.z + v3.z;
        acc.w += v0.w + v1.w + v2.w + v3.w;
    }
    for (; p < end; p++) {
        int s = g_ssrc[p];
        float4 v = *(const float4*)&x[(long long)s * DIM + lane * 4];
        acc.x += v.x; acc.y += v.y; acc.z += v.z; acc.w += v.w;
    }
    float r = 1.0f / (float)max(end - beg, 1);
    float4 o = make_float4(acc.x * r, acc.y * r, acc.z * r, acc.w * r);
    *(float4*)&g_hmean[(long long)warp * DIM + lane * 4] = o;
}

// ---------------- tf32x3 tensor-core GEMM ----------------------------------
__device__ __forceinline__ uint32_t f2tf(float f) {
    uint32_t u;
    asm("cvt.rna.tf32.f32 %0, %1;" : "=r"(u) : "f"(f));
    return u;
}

__device__ __forceinline__ void mma_tf32(float* c, const uint32_t* a, const uint32_t* b) {
    asm volatile(
        "mma.sync.aligned.m16n8k8.row.col.f32.tf32.tf32.f32 "
        "{%0,%1,%2,%3}, {%4,%5,%6,%7}, {%8,%9}, {%0,%1,%2,%3};"
        : "+f"(c[0]), "+f"(c[1]), "+f"(c[2]), "+f"(c[3])
        : "r"(a[0]), "r"(a[1]), "r"(a[2]), "r"(a[3]), "r"(b[0]), "r"(b[1]));
}

#define SMSTRIDE 132
#define GEMM_SMEM (2 * 128 * SMSTRIDE * 4)

__global__ __launch_bounds__(256) void gemm_tc_kernel(
    const float* __restrict__ x, const float* __restrict__ hmean,
    const float* __restrict__ src_w, const float* __restrict__ dst_w,
    const float* __restrict__ src_b, const float* __restrict__ dst_b,
    float* __restrict__ ha_src, float* __restrict__ ha_dst) {
    extern __shared__ float sm[];
    float* As = sm;
    float* Ws = sm + 128 * SMSTRIDE;

    const float* A    = (blockIdx.y == 0) ? x     : hmean;
    const float* W    = (blockIdx.y == 0) ? src_w : dst_w;
    const float* bias = (blockIdx.y == 0) ? src_b : dst_b;
    float*       C    = (blockIdx.y == 0) ? ha_src : ha_dst;

    int tid = threadIdx.x;
    int rowBase = blockIdx.x * 128;

#pragma unroll
    for (int it = 0; it < 16; it++) {
        int idx = tid + it * 256;
        int r = idx >> 5;
        int c = (idx & 31) * 4;
        float4 v = make_float4(0.f, 0.f, 0.f, 0.f);
        if (rowBase + r < N_NODES)
            v = *(const float4*)&A[(long long)(rowBase + r) * DIM + c];
        *(float4*)&As[r * SMSTRIDE + c] = v;
        float4 wv = *(const float4*)&W[(long long)r * DIM + c];
        *(float4*)&Ws[r * SMSTRIDE + c] = wv;
    }
    __syncthreads();

    int wid = tid >> 5, lane = tid & 31;
    int g = lane >> 2, t = lane & 3;
    int warpM = wid & 3, warpN = wid >> 2;
    int wrow = warpM * 32, wcol = warpN * 64;

    float acc[2][8][4];
#pragma unroll
    for (int mt = 0; mt < 2; mt++)
#pragma unroll
        for (int nt = 0; nt < 8; nt++)
#pragma unroll
            for (int j = 0; j < 4; j++) acc[mt][nt][j] = 0.0f;

    for (int kt = 0; kt < 16; kt++) {
        int k0 = kt * 8;
        uint32_t ahi[2][4], alo[2][4];
#pragma unroll
        for (int mt = 0; mt < 2; mt++) {
            int r0 = wrow + mt * 16;
            float a0 = As[(r0 + g) * SMSTRIDE + k0 + t];
            float a1 = As[(r0 + g + 8) * SMSTRIDE + k0 + t];
            float a2 = As[(r0 + g) * SMSTRIDE + k0 + t + 4];
            float a3 = As[(r0 + g + 8) * SMSTRIDE + k0 + t + 4];
            ahi[mt][0] = f2tf(a0); alo[mt][0] = f2tf(a0 - __uint_as_float(ahi[mt][0]));
            ahi[mt][1] = f2tf(a1); alo[mt][1] = f2tf(a1 - __uint_as_float(ahi[mt][1]));
            ahi[mt][2] = f2tf(a2); alo[mt][2] = f2tf(a2 - __uint_as_float(ahi[mt][2]));
            ahi[mt][3] = f2tf(a3); alo[mt][3] = f2tf(a3 - __uint_as_float(ahi[mt][3]));
        }
        uint32_t bhi[8][2], blo[8][2];
#pragma unroll
        for (int nt = 0; nt < 8; nt++) {
            int col = wcol + nt * 8 + g;
            float b0 = Ws[(k0 + t) * SMSTRIDE + col];
            float b1 = Ws[(k0 + t + 4) * SMSTRIDE + col];
            bhi[nt][0] = f2tf(b0); blo[nt][0] = f2tf(b0 - __uint_as_float(bhi[nt][0]));
            bhi[nt][1] = f2tf(b1); blo[nt][1] = f2tf(b1 - __uint_as_float(bhi[nt][1]));
        }
#pragma unroll
        for (int mt = 0; mt < 2; mt++)
#pragma unroll
            for (int nt = 0; nt < 8; nt++) {
                mma_tf32(acc[mt][nt], ahi[mt], blo[nt]);
                mma_tf32(acc[mt][nt], alo[mt], bhi[nt]);
                mma_tf32(acc[mt][nt], ahi[mt], bhi[nt]);
            }
    }

#pragma unroll
    for (int mt = 0; mt < 2; mt++) {
#pragma unroll
        for (int nt = 0; nt < 8; nt++) {
            int col = wcol + nt * 8 + 2 * t;
            float b0 = bias[col], b1 = bias[col + 1];
            int row0 = rowBase + wrow + mt * 16 + g;
            int row1 = row0 + 8;
            if (row0 < N_NODES) {
                float2 o0 = make_float2(acc[mt][nt][0] + b0, acc[mt][nt][1] + b1);
                *(float2*)&C[(long long)row0 * DIM + col] = o0;
            }
            if (row1 < N_NODES) {
                float2 o1 = make_float2(acc[mt][nt][2] + b0, acc[mt][nt][3] + b1);
                *(float2*)&C[(long long)row1 * DIM + col] = o1;
            }
        }
    }
}

// ------- k7: fused score + denom + weighted output, ONE pass, warp/node ----
// out[d] = (sum_e sv_e * x[src_e]) / (sum_e sv_e); normalization commutes.
__global__ __launch_bounds__(256) void fused_out_kernel(
    const float* __restrict__ x,
    const float* __restrict__ att_w,
    const float* __restrict__ att_b,
    float* __restrict__ out) {
    int warp = (blockIdx.x * blockDim.x + threadIdx.x) >> 5;
    int lane = threadIdx.x & 31;
    if (warp >= N_NODES) return;
    int beg = g_off[warp];
    int end = g_off[warp + 1];

    float4 b = *(const float4*)&g_ha_dst[(long long)warp * DIM + lane * 4];
    float4 w = *(const float4*)&att_w[lane * 4];
    float  c = att_b[0];

    float denom = 0.0f;
    float4 o = make_float4(0.f, 0.f, 0.f, 0.f);
    int p = beg;
    for (; p + 1 < end; p += 2) {
        int s0 = g_ssrc[p], s1 = g_ssrc[p + 1];
        float4 a0 = *(const float4*)&g_ha_src[(long long)s0 * DIM + lane * 4];
        float4 a1 = *(const float4*)&g_ha_src[(long long)s1 * DIM + lane * 4];
        float4 x0 = *(const float4*)&x[(long long)s0 * DIM + lane * 4];
        float4 x1 = *(const float4*)&x[(long long)s1 * DIM + lane * 4];
        float t0, t1;
        {
            float v0 = a0.x + b.x, v1 = a0.y + b.y, v2 = a0.z + b.z, v3 = a0.w + b.w;
            v0 = (v0 >= 0.f) ? v0 : v0 * NEG_SLOPE;
            v1 = (v1 >= 0.f) ? v1 : v1 * NEG_SLOPE;
            v2 = (v2 >= 0.f) ? v2 : v2 * NEG_SLOPE;
            v3 = (v3 >= 0.f) ? v3 : v3 * NEG_SLOPE;
            t0 = v0 * w.x + v1 * w.y + v2 * w.z + v3 * w.w;
        }
        {
            float v0 = a1.x + b.x, v1 = a1.y + b.y, v2 = a1.z + b.z, v3 = a1.w + b.w;
            v0 = (v0 >= 0.f) ? v0 : v0 * NEG_SLOPE;
            v1 = (v1 >= 0.f) ? v1 : v1 * NEG_SLOPE;
            v2 = (v2 >= 0.f) ? v2 : v2 * NEG_SLOPE;
            v3 = (v3 >= 0.f) ? v3 : v3 * NEG_SLOPE;
            t1 = v0 * w.x + v1 * w.y + v2 * w.z + v3 * w.w;
        }
#pragma unroll
        for (int off = 16; off > 0; off >>= 1) {
            t0 += __shfl_xor_sync(0xFFFFFFFFu, t0, off);
            t1 += __shfl_xor_sync(0xFFFFFFFFu, t1, off);
        }
        float sv0 = expf(t0 + c);
        float sv1 = expf(t1 + c);
        denom += sv0 + sv1;
        o.x += sv0 * x0.x + sv1 * x1.x;
        o.y += sv0 * x0.y + sv1 * x1.y;
        o.z += sv0 * x0.z + sv1 * x1.z;
        o.w += sv0 * x0.w + sv1 * x1.w;
    }
    for (; p < end; p++) {
        int s = g_ssrc[p];
        float4 a = *(const float4*)&g_ha_src[(long long)s * DIM + lane * 4];
        float4 xv = *(const float4*)&x[(long long)s * DIM + lane * 4];
        float v0 = a.x + b.x, v1 = a.y + b.y, v2 = a.z + b.z, v3 = a.w + b.w;
        v0 = (v0 >= 0.f) ? v0 : v0 * NEG_SLOPE;
        v1 = (v1 >= 0.f) ? v1 : v1 * NEG_SLOPE;
        v2 = (v2 >= 0.f) ? v2 : v2 * NEG_SLOPE;
        v3 = (v3 >= 0.f) ? v3 : v3 * NEG_SLOPE;
        float t = v0 * w.x + v1 * w.y + v2 * w.z + v3 * w.w;
#pragma unroll
        for (int off = 16; off > 0; off >>= 1)
            t += __shfl_xor_sync(0xFFFFFFFFu, t, off);
        float sv = expf(t + c);
        denom += sv;
        o.x += sv * xv.x; o.y += sv * xv.y; o.z += sv * xv.z; o.w += sv * xv.w;
    }

    float rd = (end > beg) ? 1.0f / denom : 0.0f;
    float4 r = make_float4(o.x * rd, o.y * rd, o.z * rd, o.w * rd);
    *(float4*)&out[(long long)warp * DIM + lane * 4] = r;
}

// ---------------------------------------------------------------------------
extern "C" void kernel_launch(void* const* d_in, const int* in_sizes, int n_in,
                              void* d_out, int out_size) {
    const float* x       = (const float*)d_in[0];
    const int*   src_idx = (const int*)d_in[1];
    const int*   dst_idx = (const int*)d_in[2];
    const float* src_w   = (const float*)d_in[3];
    const float* src_b   = (const float*)d_in[4];
    const float* dst_w   = (const float*)d_in[5];
    const float* dst_b   = (const float*)d_in[6];
    const float* att_w   = (const float*)d_in[7];
    const float* att_b   = (const float*)d_in[8];
    float* out = (float*)d_out;

    (void)in_sizes; (void)n_in; (void)out_size;

    float *hmean_p, *ha_src_p, *ha_dst_p;
    cudaGetSymbolAddress((void**)&hmean_p,  g_hmean);
    cudaGetSymbolAddress((void**)&ha_src_p, g_ha_src);
    cudaGetSymbolAddress((void**)&ha_dst_p, g_ha_dst);

    cudaFuncSetAttribute(gemm_tc_kernel,
                         cudaFuncAttributeMaxDynamicSharedMemorySize, GEMM_SMEM);

    const int e4Blocks = (N_EDGES / 4 + 255) / 256;
    const int nodeWarpBlocks = (N_NODES * 32 + 255) / 256;

    zero_cnt_kernel<<<(N_NODES + 255) / 256, 256>>>();
    hist_kernel<<<e4Blocks, 256>>>(dst_idx);
    scan_a_kernel<<<SCAN_NBLK, SCAN_BLK>>>();
    scan_c_kernel<<<SCAN_NBLK, SCAN_BLK>>>();
    scatter_kernel<<<e4Blocks, 256>>>(src_idx, dst_idx);

    agg_kernel<<<nodeWarpBlocks, 256>>>(x);

    dim3 gemmGrid((N_NODES + 127) / 128, 2);
    gemm_tc_kernel<<<gemmGrid, 256, GEMM_SMEM>>>(
        x, hmean_p, src_w, dst_w, src_b, dst_b, ha_src_p, ha_dst_p);

    fused_out_kernel<<<nodeWarpBlocks, 256>>>(x, att_w, att_b, out);
}